// round 10
// baseline (speedup 1.0000x reference)
#include <cuda_runtime.h>

// y = x*2 + 5 - 3/(1+x), elementwise over 8192*8192 fp32 (64M elems).
// R10 probe: same winning shape (V=4 float4/thread, front-batched, cs hints,
// fast reciprocal) but T=128 / 32768 CTAs — doubles the schedulable CTA pool
// per SM (16 resident CTAs vs 8) for finer backfill granularity at CTA drain.
// R8 established that a deep oversubscribed CTA pool is what keeps the HBM
// queues full; this pushes that mechanism one notch further.

constexpr int V = 4;    // float4 per thread
constexpr int T = 128;  // threads per block (halved vs R9)

__global__ __launch_bounds__(T)
void elementwise_t128_kernel(const float4* __restrict__ in,
                             float4* __restrict__ out) {
    int base = blockIdx.x * (T * V) + threadIdx.x;

    float4 v[V];
#pragma unroll
    for (int k = 0; k < V; k++) {
        v[k] = __ldcs(&in[base + k * T]);   // 4 independent LDG.E.128, front-batched
    }

#pragma unroll
    for (int k = 0; k < V; k++) {
        float4 r;
        r.x = fmaf(v[k].x, 2.0f, 5.0f) - __fdividef(3.0f, 1.0f + v[k].x);
        r.y = fmaf(v[k].y, 2.0f, 5.0f) - __fdividef(3.0f, 1.0f + v[k].y);
        r.z = fmaf(v[k].z, 2.0f, 5.0f) - __fdividef(3.0f, 1.0f + v[k].z);
        r.w = fmaf(v[k].w, 2.0f, 5.0f) - __fdividef(3.0f, 1.0f + v[k].w);
        __stcs(&out[base + k * T], r);
    }
}

extern "C" void kernel_launch(void* const* d_in, const int* in_sizes, int n_in,
                              void* d_out, int out_size) {
    const float* x = (const float*)d_in[0];
    float* y = (float*)d_out;
    int n = in_sizes[0];          // 67108864 = 8192*8192
    int n4 = n >> 2;              // 16777216 float4

    // Exact tiling: 16777216 / (128*4) = 32768 blocks, no tail.
    int blocks = n4 / (T * V);
    elementwise_t128_kernel<<<blocks, T>>>(
        (const float4*)x, (float4*)y);
}